// round 9
// baseline (speedup 1.0000x reference)
#include <cuda_runtime.h>
#include <cuda_bf16.h>
#include <cstdint>

#define N_NODES 100000
#define D 32
#define TILE_NODES 64
#define TILE_VEC   (TILE_NODES * 8)   // 512 float4 per tile

// Aggregation scratch, padded by one tile so the cp.async pipeline can read
// a full final tile without OOB (padding rows are computed but never stored).
__device__ float g_agg[(N_NODES + TILE_NODES) * D];

// ---------------------------------------------------------------------------
// Scatter: 8 lanes per edge, 4 edges per warp. Each lane gathers one float4
// of the 128B source row and issues a vectorized red.global.add.v4.f32.
// At the L2/LTS byte-throughput floor (~410MB gather+RED traffic).
// ---------------------------------------------------------------------------
__global__ void scatter_kernel(const float4* __restrict__ x4,
                               const int* __restrict__ edge_index,
                               float* __restrict__ agg,
                               int n_edges) {
    int lane = threadIdx.x & 31;
    int sub  = lane >> 3;   // which of the 4 edges this warp handles
    int q    = lane & 7;    // which 16B quarter of the 128B row

    int warp0   = (blockIdx.x * blockDim.x + threadIdx.x) >> 5;
    int wstride = (gridDim.x * blockDim.x) >> 5;

    for (int e0 = warp0 * 4; e0 < n_edges; e0 += wstride * 4) {
        int e = e0 + sub;
        if (e < n_edges) {
            int src = __ldg(edge_index + e);            // row 0: src
            int dst = __ldg(edge_index + n_edges + e);  // row 1: dst

            float4 v = __ldg(&x4[(size_t)src * 8 + q]);
            float* p = agg + (size_t)dst * D + q * 4;
            asm volatile(
                "red.global.add.v4.f32 [%0], {%1, %2, %3, %4};"
                :: "l"(p), "f"(v.x), "f"(v.y), "f"(v.z), "f"(v.w)
                : "memory");
        }
    }
}

// ---------------------------------------------------------------------------
// GEMM: out = agg @ W^T, W is [32, 32].
// Persistent blocks, 256 threads = 8 warps; tile = 64 nodes (8 per warp).
// 3-stage cp.async pipeline (depth 2 in flight): the copy of tile t+2 is
// issued while tile t computes, so L2 latency hides under 256 FFMAs/tile.
// One __syncthreads per tile. W staged coalesced into padded smem once,
// then per-lane register copy (conflict-free). Node rows read as broadcast
// LDS.128; 8 independent accumulator chains per thread.
// ---------------------------------------------------------------------------
__device__ __forceinline__ void cp_async16(void* smem, const void* gmem) {
    uint32_t s = (uint32_t)__cvta_generic_to_shared(smem);
    asm volatile("cp.async.ca.shared.global [%0], [%1], 16;"
                 :: "r"(s), "l"(gmem) : "memory");
}

__global__ __launch_bounds__(256)
void gemm_kernel(const float4* __restrict__ agg4,
                 const float* __restrict__ W,
                 float* __restrict__ out,
                 int n_nodes, int ntiles) {
    __shared__ float4 As[3][TILE_VEC];  // 3 x 8KB
    __shared__ float  Ws[D * 33];       // padded, conflict-free

    int tid  = threadIdx.x;
    int lane = tid & 31;   // output feature j
    int wid  = tid >> 5;   // warp: nodes [wid*8, wid*8+8) of the tile

    // Stage W coalesced (once per block)
#pragma unroll
    for (int i = tid; i < D * D; i += 256)
        Ws[(i >> 5) * 33 + (i & 31)] = W[i];

    // Prologue: issue copies for this block's first two tiles
    int t0 = blockIdx.x;
    if (t0 < ntiles) {
        const float4* g = agg4 + (size_t)t0 * TILE_VEC;
        cp_async16(&As[0][tid], g + tid);
        cp_async16(&As[0][tid + 256], g + tid + 256);
        asm volatile("cp.async.commit_group;" ::: "memory");
    }
    int t1 = t0 + gridDim.x;
    if (t1 < ntiles) {
        const float4* g = agg4 + (size_t)t1 * TILE_VEC;
        cp_async16(&As[1][tid], g + tid);
        cp_async16(&As[1][tid + 256], g + tid + 256);
        asm volatile("cp.async.commit_group;" ::: "memory");
    }

    __syncthreads();   // Ws visible (also first pipeline barrier)

    // Lane j copies W row j to registers (bank (j+k)%32, conflict-free)
    float w[D];
#pragma unroll
    for (int k = 0; k < D; ++k) w[k] = Ws[lane * 33 + k];

    int k = 0;
    for (int tile = t0; tile < ntiles; tile += gridDim.x, ++k) {
        int buf = k % 3;

        // Wait until this tile's copy has landed (<=1 younger group pending)
        asm volatile("cp.async.wait_group 1;" ::: "memory");
        __syncthreads();

        // Issue copy for tile k+2 into the buffer freed at iteration k-1
        int nt = tile + 2 * gridDim.x;
        if (nt < ntiles) {
            int nbuf = (k + 2) % 3;
            const float4* g = agg4 + (size_t)nt * TILE_VEC;
            cp_async16(&As[nbuf][tid], g + tid);
            cp_async16(&As[nbuf][tid + 256], g + tid + 256);
            asm volatile("cp.async.commit_group;" ::: "memory");
        }

        // Compute 8 nodes per warp
        float acc[8];
#pragma unroll
        for (int r = 0; r < 8; ++r) acc[r] = 0.0f;

        const float4* Ab = &As[buf][wid * 64];
#pragma unroll
        for (int k4 = 0; k4 < 8; ++k4) {
#pragma unroll
            for (int r = 0; r < 8; ++r) {
                float4 a = Ab[r * 8 + k4];   // broadcast across lanes
                acc[r] = fmaf(a.x, w[k4 * 4 + 0], acc[r]);
                acc[r] = fmaf(a.y, w[k4 * 4 + 1], acc[r]);
                acc[r] = fmaf(a.z, w[k4 * 4 + 2], acc[r]);
                acc[r] = fmaf(a.w, w[k4 * 4 + 3], acc[r]);
            }
        }

        int node0 = tile * TILE_NODES + wid * 8;
#pragma unroll
        for (int r = 0; r < 8; ++r) {
            int node = node0 + r;
            if (node < n_nodes)
                out[(size_t)node * D + lane] = acc[r];   // coalesced
        }
    }
}

// ---------------------------------------------------------------------------
extern "C" void kernel_launch(void* const* d_in, const int* in_sizes, int n_in,
                              void* d_out, int out_size) {
    const float* x = (const float*)d_in[0];
    const int* edge_index = (const int*)d_in[1];
    const float* W = (const float*)d_in[2];
    float* out = (float*)d_out;

    int n_edges = in_sizes[1] / 2;
    int n_nodes = in_sizes[0] / D;

    float* agg;
    cudaGetSymbolAddress((void**)&agg, g_agg);

    // 1) zero the aggregation buffer (padding rows may stay garbage)
    cudaMemsetAsync(agg, 0, (size_t)N_NODES * D * sizeof(float));

    // 2) scatter-add: 4 edges per warp, vector RED, persistent grid
    {
        int threads = 256;   // 8 warps
        int blocks  = 4736;
        scatter_kernel<<<blocks, threads>>>((const float4*)x, edge_index, agg,
                                            n_edges);
    }

    // 3) GEMM: persistent cp.async-pipelined blocks (2/SM), 64-node tiles
    {
        int ntiles = (n_nodes + TILE_NODES - 1) / TILE_NODES;  // 1563
        gemm_kernel<<<296, 256>>>((const float4*)agg, W, out, n_nodes, ntiles);
    }
}